// round 7
// baseline (speedup 1.0000x reference)
#include <cuda_runtime.h>

// ---------------------------------------------------------------------------
// TalkerAttentionV2: single-token GQA decode attention + full KV-cache copy.
// B=16, HID=1024, NH=16, NKV=8, HD=128, S=4096.
// ---------------------------------------------------------------------------

namespace {
constexpr int B    = 16;
constexpr int HID  = 1024;
constexpr int NH   = 16;
constexpr int NKV  = 8;
constexpr int HD   = 128;
constexpr int S    = 4096;
constexpr int DKV  = NKV * HD;          // 1024
constexpr int NQ   = NH * HD;           // 2048
constexpr int QKV_ROWS = NQ + 2 * DKV;  // 4096
constexpr float EPS = 1e-6f;
constexpr float SCALE = 0.0883883476483184405f; // 128^-0.5
constexpr int SC   = 8;                 // S chunks per (b,kvh)
constexpr int SLEN = S / SC;            // 512
constexpr int CF4  = SLEN / 4;          // 128 float4 columns per chunk
}

// Scratch (static device globals)
__device__ __align__(16) float g_qkv[B][QKV_ROWS];      // raw q|k|v projections
__device__ __align__(16) float g_q[B][NH][HD];          // normed+roped q
__device__ __align__(16) float g_kn[B][NKV][HD];        // normed+roped new k
__device__ __align__(16) float g_pout[B][NH][SC][HD];   // partial V-weighted sums
__device__ __align__(16) float2 g_ms[B][NH][SC];        // per-chunk (max, sumexp)
__device__ __align__(16) float g_attnout[B][NQ];        // combined attention out
__device__ int g_pos[B];

// ---------------------------------------------------------------------------
// 1. QKV projection: one block per output row (4096 rows), 16 batches at once
// ---------------------------------------------------------------------------
__global__ void k_qkv(const float* __restrict__ x,
                      const float* __restrict__ Wq,
                      const float* __restrict__ Wk,
                      const float* __restrict__ Wv) {
    int r = blockIdx.x;
    const float* wrow;
    if (r < NQ)            wrow = Wq + (size_t)r * HID;
    else if (r < NQ + DKV) wrow = Wk + (size_t)(r - NQ) * HID;
    else                   wrow = Wv + (size_t)(r - NQ - DKV) * HID;

    const float4* w4 = (const float4*)wrow;
    const float4* x4 = (const float4*)x;

    float acc[B];
#pragma unroll
    for (int b = 0; b < B; b++) acc[b] = 0.0f;

#pragma unroll
    for (int i = 0; i < 2; i++) {
        int k = threadIdx.x + i * 128;      // 256 float4 per row
        float4 w = w4[k];
#pragma unroll
        for (int b = 0; b < B; b++) {
            float4 xv = x4[b * (HID / 4) + k];
            acc[b] += w.x * xv.x + w.y * xv.y + w.z * xv.z + w.w * xv.w;
        }
    }

    __shared__ float red[4][B];
    int lane = threadIdx.x & 31, warp = threadIdx.x >> 5;
#pragma unroll
    for (int b = 0; b < B; b++) {
        float v = acc[b];
#pragma unroll
        for (int o = 16; o; o >>= 1) v += __shfl_xor_sync(0xffffffffu, v, o);
        if (lane == 0) red[warp][b] = v;
    }
    __syncthreads();
    if (threadIdx.x < B) {
        float v = red[0][threadIdx.x] + red[1][threadIdx.x] +
                  red[2][threadIdx.x] + red[3][threadIdx.x];
        g_qkv[threadIdx.x][r] = v;
    }
}

// ---------------------------------------------------------------------------
// 2. RMSNorm + RoPE for q and k heads; h==0 blocks also scan the one-hot
//    update mask for pos[b]. One block per (b, head), 128 threads.
// ---------------------------------------------------------------------------
__global__ void k_normrope(const float* __restrict__ cosb,
                           const float* __restrict__ sinb,
                           const float* __restrict__ qw,
                           const float* __restrict__ kw,
                           const float* __restrict__ um) {
    int b = blockIdx.x / (NH + NKV);
    int h = blockIdx.x % (NH + NKV);
    int d = threadIdx.x;

    if (h == 0) {
        for (int s = d; s < S; s += HD)
            if (um[b * S + s] > 0.5f) g_pos[b] = s;
    }

    bool isq = (h < NH);
    float t = isq ? g_qkv[b][h * HD + d]
                  : g_qkv[b][NQ + (h - NH) * HD + d];

    float sq = t * t;
#pragma unroll
    for (int o = 16; o; o >>= 1) sq += __shfl_xor_sync(0xffffffffu, sq, o);
    __shared__ float sred[4];
    __shared__ float sn[HD];
    if ((d & 31) == 0) sred[d >> 5] = sq;
    __syncthreads();
    float tot = sred[0] + sred[1] + sred[2] + sred[3];
    float w = isq ? qw[d] : kw[d];
    float n = t * rsqrtf(tot * (1.0f / HD) + EPS) * w;
    sn[d] = n;
    __syncthreads();
    float rot = (d < HD / 2) ? -sn[d + HD / 2] : sn[d - HD / 2];
    float outv = n * cosb[b * HD + d] + rot * sinb[b * HD + d];
    if (isq) g_q[b][h][d] = outv;
    else     g_kn[b][h - NH][d] = outv;
}

// ---------------------------------------------------------------------------
// 3. Fused flash-decode chunk kernel. Grid B*NKV*SC = 1024, 256 threads.
//    launch_bounds(256, 6): cap regs so 6 CTAs fit per SM (48 warps -> MLP).
// ---------------------------------------------------------------------------
__global__ __launch_bounds__(256, 6) void k_attn(const float* __restrict__ kcache,
                                                 const float* __restrict__ vcache,
                                                 const float* __restrict__ kpm,
                                                 float* __restrict__ outk,
                                                 float* __restrict__ outv) {
    int id    = blockIdx.x;
    int chunk = id & (SC - 1);
    int kvh   = (id >> 3) & (NKV - 1);
    int b     = id >> 6;
    int s0    = chunk * SLEN;
    int t     = threadIdx.x;   // 256

    __shared__ float q0s[HD], q1s[HD], kns[HD], vns[HD];
    __shared__ __align__(16) float e0[SLEN], e1[SLEN];
    __shared__ __align__(16) float4 r0f[CF4], r1f[CF4];
    __shared__ float sr0[8], sr1[8];

    if (t < HD) {
        q0s[t] = g_q[b][2 * kvh][t];
        q1s[t] = g_q[b][2 * kvh + 1][t];
        kns[t] = g_kn[b][kvh][t];
        vns[t] = g_qkv[b][NQ + DKV + kvh * HD + t];
    }
    __syncthreads();

    int posb = g_pos[b];
    size_t rowbase = ((size_t)(b * DKV + kvh * HD) * S + s0) >> 2; // float4 idx

    // ---- Phase 1: K copy + partial scores (HD split across thread halves)
    {
        int c     = t & (CF4 - 1);
        int dbase = (t >> 7) << 6;   // 0 or 64
        int gs    = s0 + (c << 2);
        int rel   = posb - gs;
        const float4* src = (const float4*)kcache + rowbase + c;
        float4*       dst = (float4*)outk + rowbase + c;

        float a00 = 0, a01 = 0, a02 = 0, a03 = 0;
        float a10 = 0, a11 = 0, a12 = 0, a13 = 0;
#pragma unroll 4
        for (int dd = 0; dd < 64; dd++) {
            int d = dbase + dd;
            float4 v = src[(size_t)d * (S / 4)];
            if ((unsigned)rel < 4u) (&v.x)[rel] = kns[d];
            dst[(size_t)d * (S / 4)] = v;
            float q0 = q0s[d], q1 = q1s[d];
            a00 += q0 * v.x; a01 += q0 * v.y; a02 += q0 * v.z; a03 += q0 * v.w;
            a10 += q1 * v.x; a11 += q1 * v.y; a12 += q1 * v.z; a13 += q1 * v.w;
        }

        if (t >= CF4) {
            r0f[c] = make_float4(a00, a01, a02, a03);
            r1f[c] = make_float4(a10, a11, a12, a13);
        }
        __syncthreads();
        if (t < CF4) {
            float4 m = *(const float4*)(kpm + (size_t)b * S + gs);
            float4 p0 = r0f[c], p1 = r1f[c];
            *(float4*)&e0[c << 2] = make_float4(
                (a00 + p0.x) * SCALE + m.x, (a01 + p0.y) * SCALE + m.y,
                (a02 + p0.z) * SCALE + m.z, (a03 + p0.w) * SCALE + m.w);
            *(float4*)&e1[c << 2] = make_float4(
                (a10 + p1.x) * SCALE + m.x, (a11 + p1.y) * SCALE + m.y,
                (a12 + p1.z) * SCALE + m.z, (a13 + p1.w) * SCALE + m.w);
        }
        __syncthreads();
    }

    // ---- Phase 2: local softmax over the chunk (two heads)
    {
        float m0 = -1e30f, m1 = -1e30f;
        for (int s = t; s < SLEN; s += 256) {
            m0 = fmaxf(m0, e0[s]);
            m1 = fmaxf(m1, e1[s]);
        }
#pragma unroll
        for (int o = 16; o; o >>= 1) {
            m0 = fmaxf(m0, __shfl_xor_sync(0xffffffffu, m0, o));
            m1 = fmaxf(m1, __shfl_xor_sync(0xffffffffu, m1, o));
        }
        if ((t & 31) == 0) { sr0[t >> 5] = m0; sr1[t >> 5] = m1; }
        __syncthreads();
        m0 = sr0[0]; m1 = sr1[0];
#pragma unroll
        for (int w = 1; w < 8; w++) {
            m0 = fmaxf(m0, sr0[w]);
            m1 = fmaxf(m1, sr1[w]);
        }
        __syncthreads();

        float s0a = 0.0f, s1a = 0.0f;
        for (int s = t; s < SLEN; s += 256) {
            float x0 = __expf(e0[s] - m0); e0[s] = x0; s0a += x0;
            float x1 = __expf(e1[s] - m1); e1[s] = x1; s1a += x1;
        }
#pragma unroll
        for (int o = 16; o; o >>= 1) {
            s0a += __shfl_xor_sync(0xffffffffu, s0a, o);
            s1a += __shfl_xor_sync(0xffffffffu, s1a, o);
        }
        if ((t & 31) == 0) { sr0[t >> 5] = s0a; sr1[t >> 5] = s1a; }
        __syncthreads();
        if (t == 0) {
            float t0 = 0, t1 = 0;
#pragma unroll
            for (int w = 0; w < 8; w++) { t0 += sr0[w]; t1 += sr1[w]; }
            g_ms[b][2 * kvh][chunk]     = make_float2(m0, t0);
            g_ms[b][2 * kvh + 1][chunk] = make_float2(m1, t1);
        }
        __syncthreads();
    }

    // ---- Phase 3: V copy + partial weighted sums. Warp w owns d rows w,w+8,..
    {
        int warp = t >> 5, lane = t & 31;
        const float4* src = (const float4*)vcache + rowbase;
        float4*       dst = (float4*)outv + rowbase;

        for (int d = warp; d < HD; d += 8) {
            float p0 = 0.0f, p1 = 0.0f;
            size_t rb = (size_t)d * (S / 4);
#pragma unroll
            for (int it = 0; it < CF4 / 32; it++) {
                int si = it * 32 + lane;
                float4 v = src[rb + si];
                int sl = si << 2;
                int rel = posb - (s0 + sl);
                if ((unsigned)rel < 4u) (&v.x)[rel] = vns[d];
                dst[rb + si] = v;
                float4 w0 = *(const float4*)&e0[sl];
                float4 w1 = *(const float4*)&e1[sl];
                p0 += w0.x * v.x + w0.y * v.y + w0.z * v.z + w0.w * v.w;
                p1 += w1.x * v.x + w1.y * v.y + w1.z * v.z + w1.w * v.w;
            }
#pragma unroll
            for (int o = 16; o; o >>= 1) {
                p0 += __shfl_xor_sync(0xffffffffu, p0, o);
                p1 += __shfl_xor_sync(0xffffffffu, p1, o);
            }
            if (lane == 0) {
                g_pout[b][2 * kvh][chunk][d]     = p0;
                g_pout[b][2 * kvh + 1][chunk][d] = p1;
            }
        }
    }
}

// ---------------------------------------------------------------------------
// 4. Combine partial-softmax chunks. Grid B*NH, 128 threads (one per d).
// ---------------------------------------------------------------------------
__global__ void k_combine() {
    int b = blockIdx.x >> 4, h = blockIdx.x & (NH - 1);
    int d = threadIdx.x;

    float2 ms[SC];
    float po[SC];
    float M = -1e30f;
#pragma unroll
    for (int c = 0; c < SC; c++) {
        ms[c] = g_ms[b][h][c];
        po[c] = g_pout[b][h][c][d];
        M = fmaxf(M, ms[c].x);
    }
    float tot = 0.0f, acc = 0.0f;
#pragma unroll
    for (int c = 0; c < SC; c++) {
        float w = __expf(ms[c].x - M);
        tot += w * ms[c].y;
        acc += w * po[c];
    }
    g_attnout[b][h * HD + d] = acc / tot;
}

// ---------------------------------------------------------------------------
// 5. Output projection: out[b,j] = sum_r attnout[b,r] * Wo[j,r]
// ---------------------------------------------------------------------------
__global__ void k_oproj(const float* __restrict__ Wo,
                        float* __restrict__ out) {
    int j = blockIdx.x;
    const float4* w4 = (const float4*)(Wo + (size_t)j * NQ);
    float acc[B];
#pragma unroll
    for (int b = 0; b < B; b++) acc[b] = 0.0f;

#pragma unroll
    for (int i = 0; i < 2; i++) {
        int r = threadIdx.x + i * 256;     // 512 float4 per row
        float4 w = w4[r];
#pragma unroll
        for (int b = 0; b < B; b++) {
            float4 a = *(const float4*)&g_attnout[b][r << 2];
            acc[b] += w.x * a.x + w.y * a.y + w.z * a.z + w.w * a.w;
        }
    }

    __shared__ float red[8][B];
    int lane = threadIdx.x & 31, warp = threadIdx.x >> 5;
#pragma unroll
    for (int b = 0; b < B; b++) {
        float v = acc[b];
#pragma unroll
        for (int o = 16; o; o >>= 1) v += __shfl_xor_sync(0xffffffffu, v, o);
        if (lane == 0) red[warp][b] = v;
    }
    __syncthreads();
    if (threadIdx.x < B) {
        float v = 0.0f;
#pragma unroll
        for (int w = 0; w < 8; w++) v += red[w][threadIdx.x];
        out[threadIdx.x * HID + j] = v;
    }
}

// ---------------------------------------------------------------------------
// Launch
// ---------------------------------------------------------------------------
extern "C" void kernel_launch(void* const* d_in, const int* in_sizes, int n_in,
                              void* d_out, int out_size) {
    (void)in_sizes; (void)n_in; (void)out_size;
    const float* x   = (const float*)d_in[0];
    const float* rc  = (const float*)d_in[1];
    const float* rs  = (const float*)d_in[2];
    const float* kpm = (const float*)d_in[3];
    const float* um  = (const float*)d_in[4];
    const float* kc  = (const float*)d_in[5];
    const float* vc  = (const float*)d_in[6];
    const float* Wq  = (const float*)d_in[7];
    const float* Wk  = (const float*)d_in[8];
    const float* Wv  = (const float*)d_in[9];
    const float* Wo  = (const float*)d_in[10];
    const float* qw  = (const float*)d_in[11];
    const float* kw  = (const float*)d_in[12];

    float* out  = (float*)d_out;
    float* outk = out + (size_t)B * HID;
    float* outv = outk + (size_t)B * DKV * S;

    k_qkv<<<QKV_ROWS, 128>>>(x, Wq, Wk, Wv);
    k_normrope<<<B * (NH + NKV), HD>>>(rc, rs, qw, kw, um);
    k_attn<<<B * NKV * SC, 256>>>(kc, vc, kpm, outk, outv);
    k_combine<<<B * NH, HD>>>();
    k_oproj<<<HID, 256>>>(Wo, out);
}

// round 8
// speedup vs baseline: 1.3288x; 1.3288x over previous
#include <cuda_runtime.h>

// ---------------------------------------------------------------------------
// TalkerAttentionV2: single-token GQA decode attention + full KV-cache copy.
// B=16, HID=1024, NH=16, NKV=8, HD=128, S=4096.
// R8 = R3 structure (natural registers, no launch_bounds cap, plain ld/st)
//      + conflict-free float4 LDS reads of attention weights in phase 3.
// ---------------------------------------------------------------------------

namespace {
constexpr int B    = 16;
constexpr int HID  = 1024;
constexpr int NH   = 16;
constexpr int NKV  = 8;
constexpr int HD   = 128;
constexpr int S    = 4096;
constexpr int DKV  = NKV * HD;          // 1024
constexpr int NQ   = NH * HD;           // 2048
constexpr int QKV_ROWS = NQ + 2 * DKV;  // 4096
constexpr float EPS = 1e-6f;
constexpr float SCALE = 0.0883883476483184405f; // 128^-0.5
constexpr int SC   = 8;                 // S chunks per (b,kvh)
constexpr int SLEN = S / SC;            // 512
constexpr int CF4  = SLEN / 4;          // 128 float4 columns per chunk
}

// Scratch (static device globals)
__device__ __align__(16) float g_qkv[B][QKV_ROWS];      // raw q|k|v projections
__device__ __align__(16) float g_q[B][NH][HD];          // normed+roped q
__device__ __align__(16) float g_kn[B][NKV][HD];        // normed+roped new k
__device__ __align__(16) float g_pout[B][NH][SC][HD];   // partial V-weighted sums
__device__ __align__(16) float2 g_ms[B][NH][SC];        // per-chunk (max, sumexp)
__device__ __align__(16) float g_attnout[B][NQ];        // combined attention out
__device__ int g_pos[B];

// ---------------------------------------------------------------------------
// 1. QKV projection: one block per output row (4096 rows), 16 batches at once
// ---------------------------------------------------------------------------
__global__ void k_qkv(const float* __restrict__ x,
                      const float* __restrict__ Wq,
                      const float* __restrict__ Wk,
                      const float* __restrict__ Wv) {
    int r = blockIdx.x;
    const float* wrow;
    if (r < NQ)            wrow = Wq + (size_t)r * HID;
    else if (r < NQ + DKV) wrow = Wk + (size_t)(r - NQ) * HID;
    else                   wrow = Wv + (size_t)(r - NQ - DKV) * HID;

    const float4* w4 = (const float4*)wrow;
    const float4* x4 = (const float4*)x;

    float acc[B];
#pragma unroll
    for (int b = 0; b < B; b++) acc[b] = 0.0f;

#pragma unroll
    for (int i = 0; i < 2; i++) {
        int k = threadIdx.x + i * 128;      // 256 float4 per row
        float4 w = w4[k];
#pragma unroll
        for (int b = 0; b < B; b++) {
            float4 xv = x4[b * (HID / 4) + k];
            acc[b] += w.x * xv.x + w.y * xv.y + w.z * xv.z + w.w * xv.w;
        }
    }

    __shared__ float red[4][B];
    int lane = threadIdx.x & 31, warp = threadIdx.x >> 5;
#pragma unroll
    for (int b = 0; b < B; b++) {
        float v = acc[b];
#pragma unroll
        for (int o = 16; o; o >>= 1) v += __shfl_xor_sync(0xffffffffu, v, o);
        if (lane == 0) red[warp][b] = v;
    }
    __syncthreads();
    if (threadIdx.x < B) {
        float v = red[0][threadIdx.x] + red[1][threadIdx.x] +
                  red[2][threadIdx.x] + red[3][threadIdx.x];
        g_qkv[threadIdx.x][r] = v;
    }
}

// ---------------------------------------------------------------------------
// 2. RMSNorm + RoPE for q and k heads; h==0 blocks also scan the one-hot
//    update mask for pos[b]. One block per (b, head), 128 threads.
// ---------------------------------------------------------------------------
__global__ void k_normrope(const float* __restrict__ cosb,
                           const float* __restrict__ sinb,
                           const float* __restrict__ qw,
                           const float* __restrict__ kw,
                           const float* __restrict__ um) {
    int b = blockIdx.x / (NH + NKV);
    int h = blockIdx.x % (NH + NKV);
    int d = threadIdx.x;

    if (h == 0) {
        for (int s = d; s < S; s += HD)
            if (um[b * S + s] > 0.5f) g_pos[b] = s;
    }

    bool isq = (h < NH);
    float t = isq ? g_qkv[b][h * HD + d]
                  : g_qkv[b][NQ + (h - NH) * HD + d];

    float sq = t * t;
#pragma unroll
    for (int o = 16; o; o >>= 1) sq += __shfl_xor_sync(0xffffffffu, sq, o);
    __shared__ float sred[4];
    __shared__ float sn[HD];
    if ((d & 31) == 0) sred[d >> 5] = sq;
    __syncthreads();
    float tot = sred[0] + sred[1] + sred[2] + sred[3];
    float w = isq ? qw[d] : kw[d];
    float n = t * rsqrtf(tot * (1.0f / HD) + EPS) * w;
    sn[d] = n;
    __syncthreads();
    float rot = (d < HD / 2) ? -sn[d + HD / 2] : sn[d - HD / 2];
    float outv = n * cosb[b * HD + d] + rot * sinb[b * HD + d];
    if (isq) g_q[b][h][d] = outv;
    else     g_kn[b][h - NH][d] = outv;
}

// ---------------------------------------------------------------------------
// 3. Fused flash-decode chunk kernel. Grid B*NKV*SC = 1024, 256 threads.
//    NO launch_bounds occupancy cap: phase-1 loop sits at a register cliff.
// ---------------------------------------------------------------------------
__global__ __launch_bounds__(256) void k_attn(const float* __restrict__ kcache,
                                              const float* __restrict__ vcache,
                                              const float* __restrict__ kpm,
                                              float* __restrict__ outk,
                                              float* __restrict__ outv) {
    int id    = blockIdx.x;
    int chunk = id & (SC - 1);
    int kvh   = (id >> 3) & (NKV - 1);
    int b     = id >> 6;
    int s0    = chunk * SLEN;
    int t     = threadIdx.x;   // 256

    __shared__ float q0s[HD], q1s[HD], kns[HD], vns[HD];
    __shared__ __align__(16) float e0[SLEN], e1[SLEN];
    __shared__ __align__(16) float4 r0f[CF4], r1f[CF4];
    __shared__ float sr0[8], sr1[8];

    if (t < HD) {
        q0s[t] = g_q[b][2 * kvh][t];
        q1s[t] = g_q[b][2 * kvh + 1][t];
        kns[t] = g_kn[b][kvh][t];
        vns[t] = g_qkv[b][NQ + DKV + kvh * HD + t];
    }
    __syncthreads();

    int posb = g_pos[b];
    size_t rowbase = ((size_t)(b * DKV + kvh * HD) * S + s0) >> 2; // float4 idx

    // ---- Phase 1: K copy + partial scores (HD split across thread halves)
    {
        int c     = t & (CF4 - 1);
        int dbase = (t >> 7) << 6;   // 0 or 64
        int gs    = s0 + (c << 2);
        int rel   = posb - gs;
        const float4* src = (const float4*)kcache + rowbase + c;
        float4*       dst = (float4*)outk + rowbase + c;

        float a00 = 0, a01 = 0, a02 = 0, a03 = 0;
        float a10 = 0, a11 = 0, a12 = 0, a13 = 0;
#pragma unroll 4
        for (int dd = 0; dd < 64; dd++) {
            int d = dbase + dd;
            float4 v = src[(size_t)d * (S / 4)];
            if ((unsigned)rel < 4u) (&v.x)[rel] = kns[d];
            dst[(size_t)d * (S / 4)] = v;
            float q0 = q0s[d], q1 = q1s[d];
            a00 += q0 * v.x; a01 += q0 * v.y; a02 += q0 * v.z; a03 += q0 * v.w;
            a10 += q1 * v.x; a11 += q1 * v.y; a12 += q1 * v.z; a13 += q1 * v.w;
        }

        if (t >= CF4) {
            r0f[c] = make_float4(a00, a01, a02, a03);
            r1f[c] = make_float4(a10, a11, a12, a13);
        }
        __syncthreads();
        if (t < CF4) {
            float4 m = *(const float4*)(kpm + (size_t)b * S + gs);
            float4 p0 = r0f[c], p1 = r1f[c];
            *(float4*)&e0[c << 2] = make_float4(
                (a00 + p0.x) * SCALE + m.x, (a01 + p0.y) * SCALE + m.y,
                (a02 + p0.z) * SCALE + m.z, (a03 + p0.w) * SCALE + m.w);
            *(float4*)&e1[c << 2] = make_float4(
                (a10 + p1.x) * SCALE + m.x, (a11 + p1.y) * SCALE + m.y,
                (a12 + p1.z) * SCALE + m.z, (a13 + p1.w) * SCALE + m.w);
        }
        __syncthreads();
    }

    // ---- Phase 2: local softmax over the chunk (two heads)
    {
        float m0 = -1e30f, m1 = -1e30f;
        for (int s = t; s < SLEN; s += 256) {
            m0 = fmaxf(m0, e0[s]);
            m1 = fmaxf(m1, e1[s]);
        }
#pragma unroll
        for (int o = 16; o; o >>= 1) {
            m0 = fmaxf(m0, __shfl_xor_sync(0xffffffffu, m0, o));
            m1 = fmaxf(m1, __shfl_xor_sync(0xffffffffu, m1, o));
        }
        if ((t & 31) == 0) { sr0[t >> 5] = m0; sr1[t >> 5] = m1; }
        __syncthreads();
        m0 = sr0[0]; m1 = sr1[0];
#pragma unroll
        for (int w = 1; w < 8; w++) {
            m0 = fmaxf(m0, sr0[w]);
            m1 = fmaxf(m1, sr1[w]);
        }
        __syncthreads();

        float s0a = 0.0f, s1a = 0.0f;
        for (int s = t; s < SLEN; s += 256) {
            float x0 = __expf(e0[s] - m0); e0[s] = x0; s0a += x0;
            float x1 = __expf(e1[s] - m1); e1[s] = x1; s1a += x1;
        }
#pragma unroll
        for (int o = 16; o; o >>= 1) {
            s0a += __shfl_xor_sync(0xffffffffu, s0a, o);
            s1a += __shfl_xor_sync(0xffffffffu, s1a, o);
        }
        if ((t & 31) == 0) { sr0[t >> 5] = s0a; sr1[t >> 5] = s1a; }
        __syncthreads();
        if (t == 0) {
            float t0 = 0, t1 = 0;
#pragma unroll
            for (int w = 0; w < 8; w++) { t0 += sr0[w]; t1 += sr1[w]; }
            g_ms[b][2 * kvh][chunk]     = make_float2(m0, t0);
            g_ms[b][2 * kvh + 1][chunk] = make_float2(m1, t1);
        }
        __syncthreads();
    }

    // ---- Phase 3: V copy + partial weighted sums. Warp w owns d rows w,w+8,..
    //      e0/e1 read as float4 (LDS.128, conflict-free; scalar reads were
    //      4-way bank-conflicted at 16B lane stride).
    {
        int warp = t >> 5, lane = t & 31;
        const float4* src = (const float4*)vcache + rowbase;
        float4*       dst = (float4*)outv + rowbase;

        for (int d = warp; d < HD; d += 8) {
            float p0 = 0.0f, p1 = 0.0f;
            size_t rb = (size_t)d * (S / 4);
#pragma unroll
            for (int it = 0; it < CF4 / 32; it++) {
                int si = it * 32 + lane;
                float4 v = src[rb + si];
                int sl = si << 2;
                int rel = posb - (s0 + sl);
                if ((unsigned)rel < 4u) (&v.x)[rel] = vns[d];
                dst[rb + si] = v;
                float4 w0 = *(const float4*)&e0[sl];
                float4 w1 = *(const float4*)&e1[sl];
                p0 += w0.x * v.x + w0.y * v.y + w0.z * v.z + w0.w * v.w;
                p1 += w1.x * v.x + w1.y * v.y + w1.z * v.z + w1.w * v.w;
            }
#pragma unroll
            for (int o = 16; o; o >>= 1) {
                p0 += __shfl_xor_sync(0xffffffffu, p0, o);
                p1 += __shfl_xor_sync(0xffffffffu, p1, o);
            }
            if (lane == 0) {
                g_pout[b][2 * kvh][chunk][d]     = p0;
                g_pout[b][2 * kvh + 1][chunk][d] = p1;
            }
        }
    }
}

// ---------------------------------------------------------------------------
// 4. Combine partial-softmax chunks. Grid B*NH, 128 threads (one per d).
// ---------------------------------------------------------------------------
__global__ void k_combine() {
    int b = blockIdx.x >> 4, h = blockIdx.x & (NH - 1);
    int d = threadIdx.x;

    float2 ms[SC];
    float po[SC];
    float M = -1e30f;
#pragma unroll
    for (int c = 0; c < SC; c++) {
        ms[c] = g_ms[b][h][c];
        po[c] = g_pout[b][h][c][d];
        M = fmaxf(M, ms[c].x);
    }
    float tot = 0.0f, acc = 0.0f;
#pragma unroll
    for (int c = 0; c < SC; c++) {
        float w = __expf(ms[c].x - M);
        tot += w * ms[c].y;
        acc += w * po[c];
    }
    g_attnout[b][h * HD + d] = acc / tot;
}

// ---------------------------------------------------------------------------
// 5. Output projection: out[b,j] = sum_r attnout[b,r] * Wo[j,r]
// ---------------------------------------------------------------------------
__global__ void k_oproj(const float* __restrict__ Wo,
                        float* __restrict__ out) {
    int j = blockIdx.x;
    const float4* w4 = (const float4*)(Wo + (size_t)j * NQ);
    float acc[B];
#pragma unroll
    for (int b = 0; b < B; b++) acc[b] = 0.0f;

#pragma unroll
    for (int i = 0; i < 2; i++) {
        int r = threadIdx.x + i * 256;     // 512 float4 per row
        float4 w = w4[r];
#pragma unroll
        for (int b = 0; b < B; b++) {
            float4 a = *(const float4*)&g_attnout[b][r << 2];
            acc[b] += w.x * a.x + w.y * a.y + w.z * a.z + w.w * a.w;
        }
    }

    __shared__ float red[8][B];
    int lane = threadIdx.x & 31, warp = threadIdx.x >> 5;
#pragma unroll
    for (int b = 0; b < B; b++) {
        float v = acc[b];
#pragma unroll
        for (int o = 16; o; o >>= 1) v += __shfl_xor_sync(0xffffffffu, v, o);
        if (lane == 0) red[warp][b] = v;
    }
    __syncthreads();
    if (threadIdx.x < B) {
        float v = 0.0f;
#pragma unroll
        for (int w = 0; w < 8; w++) v += red[w][threadIdx.x];
        out[threadIdx.x * HID + j] = v;
    }
}

// ---------------------------------------------------------------------------
// Launch
// ---------------------------------------------------------------------------
extern "C" void kernel_launch(void* const* d_in, const int* in_sizes, int n_in,
                              void* d_out, int out_size) {
    (void)in_sizes; (void)n_in; (void)out_size;
    const float* x   = (const float*)d_in[0];
    const float* rc  = (const float*)d_in[1];
    const float* rs  = (const float*)d_in[2];
    const float* kpm = (const float*)d_in[3];
    const float* um  = (const float*)d_in[4];
    const float* kc  = (const float*)d_in[5];
    const float* vc  = (const float*)d_in[6];
    const float* Wq  = (const float*)d_in[7];
    const float* Wk  = (const float*)d_in[8];
    const float* Wv  = (const float*)d_in[9];
    const float* Wo  = (const float*)d_in[10];
    const float* qw  = (const float*)d_in[11];
    const float* kw  = (const float*)d_in[12];

    float* out  = (float*)d_out;
    float* outk = out + (size_t)B * HID;
    float* outv = outk + (size_t)B * DKV * S;

    k_qkv<<<QKV_ROWS, 128>>>(x, Wq, Wk, Wv);
    k_normrope<<<B * (NH + NKV), HD>>>(rc, rs, qw, kw, um);
    k_attn<<<B * NKV * SC, 256>>>(kc, vc, kpm, outk, outv);
    k_combine<<<B * NH, HD>>>();
    k_oproj<<<HID, 256>>>(Wo, out);
}